// round 9
// baseline (speedup 1.0000x reference)
#include <cuda_runtime.h>
#include <cuda_bf16.h>
#include <cstdint>

// B=16, H=90, LP=512, W*L=65536, K=384
// out = mean_{b,h,j} (cs[b,h,j] - cs_p[b,h,pos[b,j]])^2
// pos[b] = ascending indices where mask[b]==1 (exactly K per batch).

#define B_     16
#define H_     90
#define LP_    512
#define WL_    65536
#define K_     384
#define NBB_   10                   // blocks per batch (2 scanners + 8 pure gatherers)
#define HPB_   (H_ / NBB_)          // 9 heads per block
#define GRID_  (B_ * NBB_)          // 160 blocks, one co-resident wave
#define NE_    (HPB_ * K_)          // 3456 gathered elements per block
#define HALF_  (WL_ / 2)            // 32768 mask ints per scanner

__device__ int      g_pos[B_ * K_];
__device__ unsigned g_ready[B_];    // 2 == both halves' positions published
__device__ unsigned g_bdone[B_];    // per-batch finish count (resets g_ready)
__device__ unsigned g_done;         // global finish count (writes out)
__device__ float    g_sum;

// evict_last loads: keep the ~79MB hot set L2-resident across graph replays
__device__ __forceinline__ float ldg_el_f32(const float* p) {
    float v;
    asm("{\n\t"
        ".reg .b64 pol;\n\t"
        "createpolicy.fractional.L2::evict_last.b64 pol, 1.0;\n\t"
        "ld.global.nc.L2::cache_hint.f32 %0, [%1], pol;\n\t"
        "}"
        : "=f"(v) : "l"(p));
    return v;
}

__device__ __forceinline__ int4 ldg_el_int4(const int4* p) {
    int4 v;
    asm("{\n\t"
        ".reg .b64 pol;\n\t"
        "createpolicy.fractional.L2::evict_last.b64 pol, 1.0;\n\t"
        "ld.global.nc.L2::cache_hint.v4.b32 {%0,%1,%2,%3}, [%4], pol;\n\t"
        "}"
        : "=r"(v.x), "=r"(v.y), "=r"(v.z), "=r"(v.w) : "l"(p));
    return v;
}

// ---------------------------------------------------------------------------
// One launch. Per batch: blocks l=0,1 scan mask half l (128KB each) and
// publish positions into g_pos[b] — half 0 ascending from 0, half 1 writes at
// [K - c1, K) (no cross-scanner dependency since c0 + c1 = K). All 10 blocks
// of the batch then spin on g_ready[b]==2 and gather their 9 heads.
// ---------------------------------------------------------------------------
__global__ void __launch_bounds__(512) fused_pc_kernel(
    const float* __restrict__ cs, const float* __restrict__ cs_p,
    const int* __restrict__ mask, float* __restrict__ out)
{
    const int t    = threadIdx.x;
    const int lane = t & 31;
    const int wid  = t >> 5;                        // 0..15
    const int b    = blockIdx.x / NBB_;
    const int l    = blockIdx.x % NBB_;

    __shared__ int   warpsums[16];
    __shared__ float wsum[16];

    // ---- scanners: pack + scan + publish positions ----
    if (l < 2) {
        // thread t owns 64 ints of this half (16 x int4) -> 2 bitmask words
        const int4* mb = reinterpret_cast<const int4*>(
            mask + (size_t)b * WL_ + l * HALF_) + t * 16;
        unsigned w[2];
#pragma unroll
        for (int g = 0; g < 2; g++) {
            int4 v[8];
#pragma unroll
            for (int i = 0; i < 8; i++) v[i] = ldg_el_int4(mb + g * 8 + i);
            unsigned x = 0;
#pragma unroll
            for (int i = 0; i < 8; i++) {
                x |= (unsigned)(v[i].x != 0) << (4 * i + 0);
                x |= (unsigned)(v[i].y != 0) << (4 * i + 1);
                x |= (unsigned)(v[i].z != 0) << (4 * i + 2);
                x |= (unsigned)(v[i].w != 0) << (4 * i + 3);
            }
            w[g] = x;
        }

        const int cnt = __popc(w[0]) + __popc(w[1]);
        int inc = cnt;
#pragma unroll
        for (int o = 1; o < 32; o <<= 1) {
            int y = __shfl_up_sync(0xffffffffu, inc, o);
            if (lane >= o) inc += y;
        }
        if (lane == 31) warpsums[wid] = inc;
        __syncthreads();
        if (wid == 0 && lane < 16) {
            int y = warpsums[lane];
#pragma unroll
            for (int o = 1; o < 16; o <<= 1) {
                int z = __shfl_up_sync(0x0000ffffu, y, o);
                if (lane >= o) y += z;
            }
            warpsums[lane] = y;
        }
        __syncthreads();

        const int prefix = (inc - cnt) + (wid > 0 ? warpsums[wid - 1] : 0);
        const int total  = warpsums[15];           // this half's one-count
        int off = (l == 0) ? prefix : (K_ - total + prefix);

        int* posb = g_pos + b * K_;
        const int base = l * HALF_ + t * 64;
#pragma unroll
        for (int g = 0; g < 2; g++) {
            unsigned x = w[g];
            while (x) {
                const int i = __ffs(x) - 1;
                posb[off++] = base + g * 32 + i;
                x &= x - 1;
            }
        }
        __syncthreads();
        if (t == 0) {
            __threadfence();                       // publish g_pos half
            atomicAdd(&g_ready[b], 1u);
        }
    }

    // ---- all blocks: wait until both halves of this batch are published ----
    if (t == 0) {
        volatile unsigned* r = g_ready + b;
        while (*r < 2u) __nanosleep(64);
        __threadfence();                           // acquire
    }
    __syncthreads();

    // ---- gather + MSE over 9 heads x 384 cols = 3456 elements ----
    const size_t bh0 = (size_t)(b * H_) + (size_t)l * HPB_;
    float sacc = 0.0f;
#pragma unroll
    for (int it = 0; it < (NE_ + 511) / 512; it++) {
        const int e = t + it * 512;
        if (e < NE_) {
            const int h = e / K_;
            const int j = e - h * K_;
            const int p = __ldg(g_pos + b * K_ + j);
            const float c = ldg_el_f32(cs_p + (bh0 + h) * WL_ + p);
            const float a = __ldg(cs + (bh0 + h) * LP_ + j);
            const float d = a - c;
            sacc = fmaf(d, d, sacc);
        }
    }

    // block reduce (16 warps)
#pragma unroll
    for (int o = 16; o > 0; o >>= 1)
        sacc += __shfl_down_sync(0xffffffffu, sacc, o);
    if (lane == 0) wsum[wid] = sacc;
    __syncthreads();

    // ---- finalize ----
    if (t == 0) {
        float v = 0.0f;
#pragma unroll
        for (int i = 0; i < 16; i++) v += wsum[i];
        atomicAdd(&g_sum, v);
        __threadfence();
        // per-batch state reset (all 10 blocks passed the spin already)
        if (atomicAdd(&g_bdone[b], 1u) == NBB_ - 1u) {
            g_ready[b] = 0u;
            g_bdone[b] = 0u;
        }
        // global finalize
        if (atomicAdd(&g_done, 1u) == GRID_ - 1u) {
            const float total = *((volatile float*)&g_sum);
            const float scale = 1.0f / ((float)B_ * (float)H_ * (float)K_);
            out[0] = total * scale;
            g_sum = 0.0f;                          // reset for next replay
            __threadfence();
            g_done = 0u;
        }
    }
}

extern "C" void kernel_launch(void* const* d_in, const int* in_sizes, int n_in,
                              void* d_out, int out_size)
{
    const float* cs   = (const float*)d_in[0];  // (B, H, LP)
    const float* cs_p = (const float*)d_in[1];  // (B, H, W, L)
    const int*   mask = (const int*)d_in[2];    // (B, W, L)
    float* out = (float*)d_out;

    fused_pc_kernel<<<GRID_, 512>>>(cs, cs_p, mask, out);
}

// round 11
// speedup vs baseline: 1.0292x; 1.0292x over previous
#include <cuda_runtime.h>
#include <cuda_bf16.h>
#include <cstdint>

// B=16, H=90, LP=512, W*L=65536, K=384
// out = mean_{b,h,j} (cs[b,h,j] - cs_p[b,h,pos[b,j]])^2
// pos[b] = ascending indices where mask[b]==1 (exactly K per batch).

#define B_      16
#define H_      90
#define LP_     512
#define WL_     65536
#define K_      384
#define HB_     3                    // heads per gatherer block
#define GPB_    (H_ / HB_)           // 30 gatherer blocks per batch
#define NGATH_  (B_ * GPB_)          // 480 gatherer blocks
#define NSCAN_  (B_ * 2)             // 32 scanner blocks (half-batch each)
#define GRID_   (NSCAN_ + NGATH_)    // 512
#define NE_     (HB_ * K_)           // 1152 elements per gatherer
#define HALF_   (WL_ / 2)            // 32768 ints per scanner

__device__ int      g_pos[B_ * K_];
__device__ unsigned g_ready[B_];     // ==2 when both halves published
__device__ unsigned g_bdone[B_];     // per-batch gatherer finish count
__device__ unsigned g_done;          // global gatherer finish count
__device__ float    g_sum;

// evict_last loads: keep the ~75MB hot set L2-resident across graph replays
__device__ __forceinline__ float ldg_el_f32(const float* p) {
    float v;
    asm("{\n\t"
        ".reg .b64 pol;\n\t"
        "createpolicy.fractional.L2::evict_last.b64 pol, 1.0;\n\t"
        "ld.global.nc.L2::cache_hint.f32 %0, [%1], pol;\n\t"
        "}"
        : "=f"(v) : "l"(p));
    return v;
}

__device__ __forceinline__ int4 ldg_el_int4(const int4* p) {
    int4 v;
    asm("{\n\t"
        ".reg .b64 pol;\n\t"
        "createpolicy.fractional.L2::evict_last.b64 pol, 1.0;\n\t"
        "ld.global.nc.L2::cache_hint.v4.b32 {%0,%1,%2,%3}, [%4], pol;\n\t"
        "}"
        : "=r"(v.x), "=r"(v.y), "=r"(v.z), "=r"(v.w) : "l"(p));
    return v;
}

// coherent L2 load (for same-kernel-written g_pos)
__device__ __forceinline__ int ldg_cg_s32(const int* p) {
    int v;
    asm volatile("ld.global.cg.s32 %0, [%1];" : "=r"(v) : "l"(p));
    return v;
}

// ---------------------------------------------------------------------------
// One launch, 512 blocks x 512 threads.
//  blocks [0,32):   scanners. Block 2b+l scans mask half l of batch b,
//                   publishes positions (half 0 ascending from 0, half 1 at
//                   [K-c1, K) -- independent since c0+c1=K). Publish protocol:
//                   ALL threads fence after their stores, bar.sync, then t0
//                   release-adds g_ready[b].
//  blocks [32,512): gatherers, 3 heads each (R4's proven 480-block shape).
//                   Preload cs into regs (overlaps scan), spin on g_ready,
//                   .cg-load pos to smem, gather cs_p, reduce, last-done
//                   block writes out and resets all state.
// Deadlock-free: scanners are grid-front (wave-1 resident), never wait.
// ---------------------------------------------------------------------------
__global__ void __launch_bounds__(512, 4) fused_ws_kernel(
    const float* __restrict__ cs, const float* __restrict__ cs_p,
    const int* __restrict__ mask, float* __restrict__ out)
{
    const int t    = threadIdx.x;
    const int lane = t & 31;
    const int wid  = t >> 5;                      // 0..15

    __shared__ int warpsums[16];

    // ================= scanner blocks =================
    if (blockIdx.x < NSCAN_) {
        const int b = blockIdx.x >> 1;
        const int l = blockIdx.x & 1;

        // 16 int4 = 64 ints per thread -> 2 bitmask words
        const int4* mb = reinterpret_cast<const int4*>(
            mask + (size_t)b * WL_ + l * HALF_) + t * 16;
        unsigned w[2];
#pragma unroll
        for (int g = 0; g < 2; g++) {
            int4 v[8];
#pragma unroll
            for (int i = 0; i < 8; i++) v[i] = ldg_el_int4(mb + g * 8 + i);
            unsigned x = 0;
#pragma unroll
            for (int i = 0; i < 8; i++) {
                x |= (unsigned)(v[i].x != 0) << (4 * i + 0);
                x |= (unsigned)(v[i].y != 0) << (4 * i + 1);
                x |= (unsigned)(v[i].z != 0) << (4 * i + 2);
                x |= (unsigned)(v[i].w != 0) << (4 * i + 3);
            }
            w[g] = x;
        }

        const int cnt = __popc(w[0]) + __popc(w[1]);
        int inc = cnt;
#pragma unroll
        for (int o = 1; o < 32; o <<= 1) {
            int y = __shfl_up_sync(0xffffffffu, inc, o);
            if (lane >= o) inc += y;
        }
        if (lane == 31) warpsums[wid] = inc;
        __syncthreads();
        if (wid == 0 && lane < 16) {
            int y = warpsums[lane];
#pragma unroll
            for (int o = 1; o < 16; o <<= 1) {
                int z = __shfl_up_sync(0x0000ffffu, y, o);
                if (lane >= o) y += z;
            }
            warpsums[lane] = y;
        }
        __syncthreads();

        const int prefix = (inc - cnt) + (wid > 0 ? warpsums[wid - 1] : 0);
        const int total  = warpsums[15];
        int off = (l == 0) ? prefix : (K_ - total + prefix);

        int* posb = g_pos + b * K_;
        const int base = l * HALF_ + t * 64;
#pragma unroll
        for (int g = 0; g < 2; g++) {
            unsigned x = w[g];
            while (x) {
                const int i = __ffs(x) - 1;
                posb[off++] = base + g * 32 + i;
                x &= x - 1;
            }
        }
        // publish: EVERY thread fences its own stores, then barrier, then
        // t0's release-add. (t0-only fencing was the R10 correctness bug.)
        __threadfence();
        __syncthreads();
        if (t == 0)
            atomicAdd(&g_ready[b], 1u);
        return;
    }

    // ================= gatherer blocks =================
    const int gidx = blockIdx.x - NSCAN_;         // 0..479
    const int b    = gidx / GPB_;
    const int h0   = (gidx % GPB_) * HB_;
    const size_t bh0 = (size_t)(b * H_ + h0);

    __shared__ int   spos[K_];
    __shared__ float wsum[16];

    // preload cs (independent of scan -> overlaps it)
    float a[3];
    bool  pred[3];
    int   hh[3], jj[3];
#pragma unroll
    for (int r = 0; r < 3; r++) {
        const int e = t + r * 512;
        pred[r] = (e < NE_);
        hh[r] = pred[r] ? (e / K_) : 0;
        jj[r] = e - (e / K_) * K_;
        a[r] = pred[r] ? __ldg(cs + (bh0 + hh[r]) * LP_ + jj[r]) : 0.0f;
    }

    // wait for this batch's positions
    if (t == 0) {
        volatile unsigned* r = g_ready + b;
        while (*r < 2u) __nanosleep(32);
        __threadfence();                           // acquire
    }
    __syncthreads();

    if (t < K_) spos[t] = ldg_cg_s32(g_pos + b * K_ + t);   // coherent L2 load
    __syncthreads();

    // gather (3 independent loads in flight per thread)
    float c[3];
#pragma unroll
    for (int r = 0; r < 3; r++)
        c[r] = pred[r] ? ldg_el_f32(cs_p + (bh0 + hh[r]) * WL_ + spos[jj[r]]) : 0.0f;

    float sacc = 0.0f;
#pragma unroll
    for (int r = 0; r < 3; r++) {
        const float d = a[r] - c[r];
        sacc = fmaf(d, d, sacc);
    }

    // block reduce (16 warps)
#pragma unroll
    for (int o = 16; o > 0; o >>= 1)
        sacc += __shfl_down_sync(0xffffffffu, sacc, o);
    if (lane == 0) wsum[wid] = sacc;
    __syncthreads();

    if (t == 0) {
        float v = 0.0f;
#pragma unroll
        for (int i = 0; i < 16; i++) v += wsum[i];
        atomicAdd(&g_sum, v);
        __threadfence();
        // per-batch reset (all 30 gatherers of b have passed the spin)
        if (atomicAdd(&g_bdone[b], 1u) == GPB_ - 1u) {
            g_ready[b] = 0u;
            g_bdone[b] = 0u;
        }
        // global finalize
        if (atomicAdd(&g_done, 1u) == NGATH_ - 1u) {
            const float total = *((volatile float*)&g_sum);
            const float scale = 1.0f / ((float)B_ * (float)H_ * (float)K_);
            out[0] = total * scale;
            g_sum = 0.0f;
            __threadfence();
            g_done = 0u;
        }
    }
}

extern "C" void kernel_launch(void* const* d_in, const int* in_sizes, int n_in,
                              void* d_out, int out_size)
{
    const float* cs   = (const float*)d_in[0];  // (B, H, LP)
    const float* cs_p = (const float*)d_in[1];  // (B, H, W, L)
    const int*   mask = (const int*)d_in[2];    // (B, W, L)
    float* out = (float*)d_out;

    fused_ws_kernel<<<GRID_, 512>>>(cs, cs_p, mask, out);
}

// round 12
// speedup vs baseline: 1.2718x; 1.2357x over previous
#include <cuda_runtime.h>
#include <cuda_bf16.h>
#include <cstdint>

// B=16, H=90, LP=512, W*L=65536, K=384
// out = mean_{b,h,j} (cs[b,h,j] - cs_p[b,h,pos[b,j]])^2
// pos[b] = ascending indices where mask[b]==1 (exactly K per batch).

#define B_      16
#define H_      90
#define LP_     512
#define WL_     65536
#define K_      384
#define HB_     3                    // heads per gatherer block
#define GPB_    (H_ / HB_)           // 30 gatherer blocks per batch
#define NGATH_  (B_ * GPB_)          // 480 gatherer blocks
#define NSCAN_  (B_ * 2)             // 32 scanner blocks (half-batch each)
#define HALF_   (WL_ / 2)            // 32768 ints per scanner

__device__ int g_pos[B_ * K_];

// evict_last loads: keep the ~75MB hot set L2-resident across graph replays
__device__ __forceinline__ float ldg_el_f32(const float* p) {
    float v;
    asm("{\n\t"
        ".reg .b64 pol;\n\t"
        "createpolicy.fractional.L2::evict_last.b64 pol, 1.0;\n\t"
        "ld.global.nc.L2::cache_hint.f32 %0, [%1], pol;\n\t"
        "}"
        : "=f"(v) : "l"(p));
    return v;
}

__device__ __forceinline__ int4 ldg_el_int4(const int4* p) {
    int4 v;
    asm("{\n\t"
        ".reg .b64 pol;\n\t"
        "createpolicy.fractional.L2::evict_last.b64 pol, 1.0;\n\t"
        "ld.global.nc.L2::cache_hint.v4.b32 {%0,%1,%2,%3}, [%4], pol;\n\t"
        "}"
        : "=r"(v.x), "=r"(v.y), "=r"(v.z), "=r"(v.w) : "l"(p));
    return v;
}

// coherent L2 load for g_pos (written by the primary grid)
__device__ __forceinline__ int ldg_cg_s32(const int* p) {
    int v;
    asm volatile("ld.global.cg.s32 %0, [%1];" : "=r"(v) : "l"(p));
    return v;
}

// ---------------------------------------------------------------------------
// PRIMARY: 32 blocks x 512 threads. Block 2b+l scans mask half l of batch b
// (32768 ints, 16 int4/thread), popcount block-scan, publishes positions:
// half 0 ascending from 0, half 1 descending into [K-c1, K) (independent
// because c0 + c1 = K). Also zeroes out[0]. Triggers PDL at the end.
// ---------------------------------------------------------------------------
__global__ void __launch_bounds__(512) scan_kernel(
    const int* __restrict__ mask, float* __restrict__ out)
{
    const int t    = threadIdx.x;
    const int lane = t & 31;
    const int wid  = t >> 5;                      // 0..15
    const int b    = blockIdx.x >> 1;
    const int l    = blockIdx.x & 1;

    if (blockIdx.x == 0 && t == 0) out[0] = 0.0f;   // d_out poisoned

    __shared__ int warpsums[16];

    // pack: 16 int4 = 64 ints per thread -> 2 bitmask words
    const int4* mb = reinterpret_cast<const int4*>(
        mask + (size_t)b * WL_ + l * HALF_) + t * 16;
    unsigned w[2];
#pragma unroll
    for (int g = 0; g < 2; g++) {
        int4 v[8];
#pragma unroll
        for (int i = 0; i < 8; i++) v[i] = ldg_el_int4(mb + g * 8 + i);
        unsigned x = 0;
#pragma unroll
        for (int i = 0; i < 8; i++) {
            x |= (unsigned)(v[i].x != 0) << (4 * i + 0);
            x |= (unsigned)(v[i].y != 0) << (4 * i + 1);
            x |= (unsigned)(v[i].z != 0) << (4 * i + 2);
            x |= (unsigned)(v[i].w != 0) << (4 * i + 3);
        }
        w[g] = x;
    }

    // block scan of popcounts
    const int cnt = __popc(w[0]) + __popc(w[1]);
    int inc = cnt;
#pragma unroll
    for (int o = 1; o < 32; o <<= 1) {
        int y = __shfl_up_sync(0xffffffffu, inc, o);
        if (lane >= o) inc += y;
    }
    if (lane == 31) warpsums[wid] = inc;
    __syncthreads();
    if (wid == 0 && lane < 16) {
        int y = warpsums[lane];
#pragma unroll
        for (int o = 1; o < 16; o <<= 1) {
            int z = __shfl_up_sync(0x0000ffffu, y, o);
            if (lane >= o) y += z;
        }
        warpsums[lane] = y;
    }
    __syncthreads();

    const int prefix = (inc - cnt) + (wid > 0 ? warpsums[wid - 1] : 0);
    const int total  = warpsums[15];              // this half's one-count
    int off = (l == 0) ? prefix : (K_ - total + prefix);

    int* posb = g_pos + b * K_;
    const int base = l * HALF_ + t * 64;
#pragma unroll
    for (int g = 0; g < 2; g++) {
        unsigned x = w[g];
        while (x) {
            const int i = __ffs(x) - 1;
            posb[off++] = base + g * 32 + i;
            x &= x - 1;
        }
    }

    __threadfence();
    __syncthreads();
    cudaTriggerProgrammaticLaunchCompletion();    // writes done -> let PDL fire
}

// ---------------------------------------------------------------------------
// SECONDARY (PDL): 480 blocks x 384 threads — R4's proven gather shape.
// Preamble (cs preload, index math) runs overlapped with the primary; then
// cudaGridDependencySynchronize() waits (HW, no spin) for the scan, then
// gather + reduce + atomicAdd(out).
// ---------------------------------------------------------------------------
__global__ void __launch_bounds__(K_) mse_kernel(
    const float* __restrict__ cs, const float* __restrict__ cs_p,
    float* __restrict__ out)
{
    const int blk = blockIdx.x;                   // 0 .. 479
    const int b   = blk / GPB_;
    const int h0  = (blk % GPB_) * HB_;
    const int j   = threadIdx.x;                  // 0 .. 383

    const float* csb  = cs + ((size_t)(b * H_ + h0)) * LP_ + j;

    // p-independent preamble: overlaps the scanner
    float a[HB_];
#pragma unroll
    for (int r = 0; r < HB_; r++) a[r] = __ldg(csb + (size_t)r * LP_);

    // HW wait for the primary grid (memory fully visible after this)
    cudaGridDependencySynchronize();

    const int p = ldg_cg_s32(g_pos + b * K_ + j);
    const float* cspb = cs_p + ((size_t)(b * H_ + h0)) * WL_ + p;

    float c[HB_];
#pragma unroll
    for (int r = 0; r < HB_; r++) c[r] = ldg_el_f32(cspb + (size_t)r * WL_);

    float s = 0.0f;
#pragma unroll
    for (int r = 0; r < HB_; r++) { float d = a[r] - c[r]; s = fmaf(d, d, s); }

    // block reduce (384 threads = 12 warps)
    const int lane = j & 31;
    const int wid  = j >> 5;
#pragma unroll
    for (int o = 16; o > 0; o >>= 1)
        s += __shfl_down_sync(0xffffffffu, s, o);

    __shared__ float wsum[12];
    if (lane == 0) wsum[wid] = s;
    __syncthreads();

    if (wid == 0) {
        float v = (lane < 12) ? wsum[lane] : 0.0f;
#pragma unroll
        for (int o = 16; o > 0; o >>= 1)
            v += __shfl_down_sync(0xffffffffu, v, o);
        if (lane == 0) {
            const float scale = 1.0f / ((float)B_ * (float)H_ * (float)K_);
            atomicAdd(out, v * scale);
        }
    }
}

extern "C" void kernel_launch(void* const* d_in, const int* in_sizes, int n_in,
                              void* d_out, int out_size)
{
    const float* cs   = (const float*)d_in[0];  // (B, H, LP)
    const float* cs_p = (const float*)d_in[1];  // (B, H, W, L)
    const int*   mask = (const int*)d_in[2];    // (B, W, L)
    float* out = (float*)d_out;

    // primary
    scan_kernel<<<NSCAN_, 512>>>(mask, out);

    // secondary with programmatic dependent launch (overlaps primary)
    cudaLaunchConfig_t cfg = {};
    cfg.gridDim  = dim3(NGATH_);
    cfg.blockDim = dim3(K_);
    cfg.dynamicSmemBytes = 0;
    cfg.stream = 0;                                // same (capture) stream
    cudaLaunchAttribute attr[1];
    attr[0].id = cudaLaunchAttributeProgrammaticStreamSerialization;
    attr[0].val.programmaticStreamSerializationAllowed = 1;
    cfg.attrs = attr;
    cfg.numAttrs = 1;
    cudaLaunchKernelEx(&cfg, mse_kernel, cs, cs_p, out);
}

// round 13
// speedup vs baseline: 1.7827x; 1.4018x over previous
#include <cuda_runtime.h>
#include <cuda_bf16.h>
#include <cstdint>

// B=16, H=90, LP=512, W*L=65536, K=384
// out = mean_{b,h,j} (cs[b,h,j] - cs_p[b,h,pos[b,j]])^2
// pos[b] = ascending indices where mask[b]==1 (exactly K per batch).

#define B_      16
#define H_      90
#define LP_     512
#define WL_     65536
#define K_      384
#define HB_     3                    // heads per gatherer block
#define GPB_    (H_ / HB_)           // 30 gatherer blocks per batch
#define NGATH_  (B_ * GPB_)          // 480 gatherer blocks
#define SEG_    16                   // segments per batch
#define SEGSZ_  (WL_ / SEG_)         // 4096 mask ints per segment
#define NSCAN_  (B_ * SEG_)          // 256 scanner blocks

__device__ int      g_pos_seg[B_ * SEG_ * K_];   // seg-local ascending positions
__device__ unsigned g_cnt[B_ * SEG_];            // ones per segment

// evict_last loads: keep the ~75MB hot set L2-resident across graph replays
__device__ __forceinline__ float ldg_el_f32(const float* p) {
    float v;
    asm("{\n\t"
        ".reg .b64 pol;\n\t"
        "createpolicy.fractional.L2::evict_last.b64 pol, 1.0;\n\t"
        "ld.global.nc.L2::cache_hint.f32 %0, [%1], pol;\n\t"
        "}"
        : "=f"(v) : "l"(p));
    return v;
}

__device__ __forceinline__ int4 ldg_el_int4(const int4* p) {
    int4 v;
    asm("{\n\t"
        ".reg .b64 pol;\n\t"
        "createpolicy.fractional.L2::evict_last.b64 pol, 1.0;\n\t"
        "ld.global.nc.L2::cache_hint.v4.b32 {%0,%1,%2,%3}, [%4], pol;\n\t"
        "}"
        : "=r"(v.x), "=r"(v.y), "=r"(v.z), "=r"(v.w) : "l"(p));
    return v;
}

// coherent L2 loads for data written by the primary grid
__device__ __forceinline__ int ldg_cg_s32(const int* p) {
    int v;
    asm volatile("ld.global.cg.s32 %0, [%1];" : "=r"(v) : "l"(p));
    return v;
}
__device__ __forceinline__ unsigned ldg_cg_u32(const unsigned* p) {
    unsigned v;
    asm volatile("ld.global.cg.u32 %0, [%1];" : "=r"(v) : "l"(p));
    return v;
}

// ---------------------------------------------------------------------------
// PRIMARY: 256 blocks x 512 threads. Block (b, s) scans segment s of batch b
// (4096 ints, 2 int4/thread) and publishes SEGMENT-LOCAL positions + count.
// No cross-block communication; full-chip parallel. Triggers PDL at the end.
// ---------------------------------------------------------------------------
__global__ void __launch_bounds__(512) scan_kernel(
    const int* __restrict__ mask, float* __restrict__ out)
{
    const int t    = threadIdx.x;
    const int lane = t & 31;
    const int wid  = t >> 5;                      // 0..15
    const int b    = blockIdx.x / SEG_;
    const int s    = blockIdx.x % SEG_;

    if (blockIdx.x == 0 && t == 0) out[0] = 0.0f;   // d_out poisoned

    __shared__ int warpsums[16];

    // pack: 2 int4 = 8 ints per thread -> 8 bits
    const int4* mb = reinterpret_cast<const int4*>(
        mask + (size_t)b * WL_ + s * SEGSZ_) + t * 2;
    const int4 v0 = ldg_el_int4(mb + 0);
    const int4 v1 = ldg_el_int4(mb + 1);
    unsigned bits = (unsigned)(v0.x != 0)
                  | ((unsigned)(v0.y != 0) << 1)
                  | ((unsigned)(v0.z != 0) << 2)
                  | ((unsigned)(v0.w != 0) << 3)
                  | ((unsigned)(v1.x != 0) << 4)
                  | ((unsigned)(v1.y != 0) << 5)
                  | ((unsigned)(v1.z != 0) << 6)
                  | ((unsigned)(v1.w != 0) << 7);

    // block scan of popcounts
    const int cnt = __popc(bits);
    int inc = cnt;
#pragma unroll
    for (int o = 1; o < 32; o <<= 1) {
        int y = __shfl_up_sync(0xffffffffu, inc, o);
        if (lane >= o) inc += y;
    }
    if (lane == 31) warpsums[wid] = inc;
    __syncthreads();
    if (wid == 0 && lane < 16) {
        int y = warpsums[lane];
#pragma unroll
        for (int o = 1; o < 16; o <<= 1) {
            int z = __shfl_up_sync(0x0000ffffu, y, o);
            if (lane >= o) y += z;
        }
        warpsums[lane] = y;
    }
    __syncthreads();

    int off = (inc - cnt) + (wid > 0 ? warpsums[wid - 1] : 0);

    int* posb = g_pos_seg + (size_t)(b * SEG_ + s) * K_;
    const int base = s * SEGSZ_ + t * 8;          // GLOBAL position of bit 0
    unsigned x = bits;
    while (x) {
        const int i = __ffs(x) - 1;
        posb[off++] = base + i;
        x &= x - 1;
    }
    if (t == 0)
        g_cnt[b * SEG_ + s] = (unsigned)warpsums[15];

    __threadfence();
    __syncthreads();
    cudaTriggerProgrammaticLaunchCompletion();
}

// ---------------------------------------------------------------------------
// SECONDARY (PDL): 480 blocks x 384 threads. Preamble (cs preload) overlaps
// the primary; after cudaGridDependencySynchronize(), reassemble global rank:
// prefix-sum the 16 segment counts (warp 0), thread j finds its segment by
// prefix comparison, reads the seg-local position, gathers, reduces.
// ---------------------------------------------------------------------------
__global__ void __launch_bounds__(K_) mse_kernel(
    const float* __restrict__ cs, const float* __restrict__ cs_p,
    float* __restrict__ out)
{
    const int blk = blockIdx.x;                   // 0 .. 479
    const int b   = blk / GPB_;
    const int h0  = (blk % GPB_) * HB_;
    const int j   = threadIdx.x;                  // 0 .. 383
    const int lane = j & 31;
    const int wid  = j >> 5;

    __shared__ int   pfx[SEG_];                   // exclusive prefix of counts
    __shared__ float wsum[12];

    const float* csb = cs + ((size_t)(b * H_ + h0)) * LP_ + j;

    // p-independent preamble: overlaps the scanner
    float a[HB_];
#pragma unroll
    for (int r = 0; r < HB_; r++) a[r] = __ldg(csb + (size_t)r * LP_);

    // HW wait for the primary grid
    cudaGridDependencySynchronize();

    // warp 0: prefix-sum the 16 segment counts
    if (wid == 0) {
        int c = (lane < SEG_) ? (int)ldg_cg_u32(g_cnt + b * SEG_ + lane) : 0;
        int incl = c;
#pragma unroll
        for (int o = 1; o < 16; o <<= 1) {
            int y = __shfl_up_sync(0xffffffffu, incl, o);
            if (lane >= o) incl += y;
        }
        if (lane < SEG_) pfx[lane] = incl - c;    // exclusive prefix
    }
    __syncthreads();

    // locate segment: s = max { k : pfx[k] <= j }
    int s = 0;
#pragma unroll
    for (int k = 1; k < SEG_; k++)
        s += (j >= pfx[k]);

    const int p = ldg_cg_s32(g_pos_seg + (size_t)(b * SEG_ + s) * K_ + (j - pfx[s]));
    const float* cspb = cs_p + ((size_t)(b * H_ + h0)) * WL_ + p;

    float c[HB_];
#pragma unroll
    for (int r = 0; r < HB_; r++) c[r] = ldg_el_f32(cspb + (size_t)r * WL_);

    float sacc = 0.0f;
#pragma unroll
    for (int r = 0; r < HB_; r++) { float d = a[r] - c[r]; sacc = fmaf(d, d, sacc); }

    // block reduce (12 warps)
#pragma unroll
    for (int o = 16; o > 0; o >>= 1)
        sacc += __shfl_down_sync(0xffffffffu, sacc, o);
    if (lane == 0) wsum[wid] = sacc;
    __syncthreads();

    if (wid == 0) {
        float v = (lane < 12) ? wsum[lane] : 0.0f;
#pragma unroll
        for (int o = 16; o > 0; o >>= 1)
            v += __shfl_down_sync(0xffffffffu, v, o);
        if (lane == 0) {
            const float scale = 1.0f / ((float)B_ * (float)H_ * (float)K_);
            atomicAdd(out, v * scale);
        }
    }
}

extern "C" void kernel_launch(void* const* d_in, const int* in_sizes, int n_in,
                              void* d_out, int out_size)
{
    const float* cs   = (const float*)d_in[0];  // (B, H, LP)
    const float* cs_p = (const float*)d_in[1];  // (B, H, W, L)
    const int*   mask = (const int*)d_in[2];    // (B, W, L)
    float* out = (float*)d_out;

    // primary: segmented scan, full-chip parallel
    scan_kernel<<<NSCAN_, 512>>>(mask, out);

    // secondary with programmatic dependent launch (overlaps primary)
    cudaLaunchConfig_t cfg = {};
    cfg.gridDim  = dim3(NGATH_);
    cfg.blockDim = dim3(K_);
    cfg.dynamicSmemBytes = 0;
    cfg.stream = 0;
    cudaLaunchAttribute attr[1];
    attr[0].id = cudaLaunchAttributeProgrammaticStreamSerialization;
    attr[0].val.programmaticStreamSerializationAllowed = 1;
    cfg.attrs = attr;
    cfg.numAttrs = 1;
    cudaLaunchKernelEx(&cfg, mse_kernel, cs, cs_p, out);
}